// round 5
// baseline (speedup 1.0000x reference)
#include <cuda_runtime.h>
#include <cuda_bf16.h>

#define NN 50000
#define NE 800000

// ---------------- device scratch (static, allocation-free) ----------------
__device__ __align__(16) float g_h [(size_t)NN * 128]; // [n][v][{h0,h1x,h1y,h1z}]
__device__ __align__(16) float g_sc[(size_t)NN * 160]; // [n][ sc_s(32) | sc_g(32) | sc_v(96) ]
__device__ __align__(16) float g_s [(size_t)NN * 256]; // [n][u][8]

// ---------------- MLP weights in constant memory (50KB, verbatim copies) ----
__constant__ __align__(16) float c_w0[512];   // fc_w0 [8][64]
__constant__ __align__(16) float c_w1[4096];  // fc_w1 [64][64]
__constant__ __align__(16) float c_w2[8192];  // fc_w2 [64][128]

__device__ __forceinline__ float silu_f(float x) {
    return __fdividef(x, 1.0f + __expf(-x));
}

__device__ __forceinline__ void red_add_v4(float* p, float a, float b, float c, float d) {
    asm volatile("red.global.add.v4.f32 [%0], {%1,%2,%3,%4};"
                 :: "l"(p), "f"(a), "f"(b), "f"(c), "f"(d) : "memory");
}

// ---- packed f32x2 helpers ----
typedef unsigned long long ull;

__device__ __forceinline__ ull pk2(float x, float y) {
    ull r; asm("mov.b64 %0, {%1,%2};" : "=l"(r) : "f"(x), "f"(y)); return r;
}
__device__ __forceinline__ void upk2(ull v, float& x, float& y) {
    asm("mov.b64 {%0,%1}, %2;" : "=f"(x), "=f"(y) : "l"(v));
}
__device__ __forceinline__ ull fma2(ull a, ull b, ull c) {
    ull d; asm("fma.rn.f32x2 %0, %1, %2, %3;" : "=l"(d) : "l"(a), "l"(b), "l"(c)); return d;
}

__global__ void k_dummy() {}

// ================= kernel 1: per-node pre (4 nodes/warp) =================
// dynamic shared floats: WS[16384] WG[16384] WV[16384] L10[1024] L11[1024] X[12*512]
#define K1_WS  0
#define K1_WG  16384
#define K1_WV  32768
#define K1_L10 49152
#define K1_L11 50176
#define K1_X   51200
#define K1_FLOATS (K1_X + 12 * 512)
#define K1_BYTES  (K1_FLOATS * 4)

__global__ void __launch_bounds__(384) k_node_pre(
    const float* __restrict__ nf,  const float* __restrict__ attr,
    const float* __restrict__ w10, const float* __restrict__ w11,
    const float* __restrict__ ws,  const float* __restrict__ wg,
    const float* __restrict__ wv)
{
    extern __shared__ float sh[];
    const float SCN = 0.044194173824159216f; // 1/sqrt(512)
    const float L1  = 0.17677669529663687f;  // 1/sqrt(32)
    int tid = threadIdx.x;

    {
        const float4* p4 = (const float4*)ws;
        for (int i = tid; i < 4096; i += 384) {
            float4 v = __ldg(p4 + i);
            v.x *= SCN; v.y *= SCN; v.z *= SCN; v.w *= SCN;
            ((float4*)(sh + K1_WS))[i] = v;
        }
        p4 = (const float4*)wg;
        for (int i = tid; i < 4096; i += 384) {
            float4 v = __ldg(p4 + i);
            v.x *= SCN; v.y *= SCN; v.z *= SCN; v.w *= SCN;
            ((float4*)(sh + K1_WG))[i] = v;
        }
        p4 = (const float4*)wv;
        for (int i = tid; i < 4096; i += 384) {
            float4 v = __ldg(p4 + i);
            v.x *= SCN; v.y *= SCN; v.z *= SCN; v.w *= SCN;
            ((float4*)(sh + K1_WV))[i] = v;
        }
        p4 = (const float4*)w10;
        for (int i = tid; i < 256; i += 384) {
            float4 v = __ldg(p4 + i);
            v.x *= L1; v.y *= L1; v.z *= L1; v.w *= L1;
            ((float4*)(sh + K1_L10))[i] = v;
        }
        p4 = (const float4*)w11;
        for (int i = tid; i < 256; i += 384) {
            float4 v = __ldg(p4 + i);
            v.x *= L1; v.y *= L1; v.z *= L1; v.w *= L1;
            ((float4*)(sh + K1_L11))[i] = v;
        }
    }
    __syncthreads();

    int warp = tid >> 5, lane = tid & 31;
    float* shx = sh + K1_X + warp * 512;

    for (int p = blockIdx.x * 12 + warp; p < NN / 4; p += gridDim.x * 12) {
        int n0 = 4 * p;
        #pragma unroll
        for (int c = 0; c < 4; c++)
            ((float4*)shx)[c * 32 + lane] =
                __ldg((const float4*)nf + (size_t)(n0 + c) * 32 + lane);
        __syncwarp();

        float z[4][16];
        #pragma unroll
        for (int c = 0; c < 4; c++) {
            const float4* zp = (const float4*)attr + (size_t)(n0 + c) * 4;
            #pragma unroll
            for (int q = 0; q < 4; q++) {
                float4 t = __ldg(zp + q);
                z[c][4 * q]     = t.x; z[c][4 * q + 1] = t.y;
                z[c][4 * q + 2] = t.z; z[c][4 * q + 3] = t.w;
            }
        }

        float as[4] = {0.f, 0.f, 0.f, 0.f}, ag[4] = {0.f, 0.f, 0.f, 0.f};
        float av[4][3] = {};
        float h0[4] = {0.f, 0.f, 0.f, 0.f};
        float h1[4][3] = {};

        #pragma unroll 1
        for (int u = 0; u < 32; u++) {
            const float* wsp = sh + u * 512 + lane;
            float ts[4] = {0.f, 0.f, 0.f, 0.f};
            float tg[4] = {0.f, 0.f, 0.f, 0.f};
            float tv[4] = {0.f, 0.f, 0.f, 0.f};
            #pragma unroll
            for (int v = 0; v < 16; v++) {
                float a  = wsp[K1_WS + v * 32];
                float b  = wsp[K1_WG + v * 32];
                float cw = wsp[K1_WV + v * 32];
                #pragma unroll
                for (int c = 0; c < 4; c++) {
                    ts[c] += z[c][v] * a;
                    tg[c] += z[c][v] * b;
                    tv[c] += z[c][v] * cw;
                }
            }
            float l10v = sh[K1_L10 + u * 32 + lane];
            float l11v = sh[K1_L11 + u * 32 + lane];
            #pragma unroll
            for (int c = 0; c < 4; c++) {
                float x0  = shx[c * 128 + u];
                float xa0 = shx[c * 128 + 32 + u * 3];
                float xa1 = shx[c * 128 + 33 + u * 3];
                float xa2 = shx[c * 128 + 34 + u * 3];
                as[c] += x0 * ts[c];  ag[c] += x0 * tg[c];
                av[c][0] += xa0 * tv[c]; av[c][1] += xa1 * tv[c]; av[c][2] += xa2 * tv[c];
                h0[c] += x0 * l10v;
                h1[c][0] += xa0 * l11v; h1[c][1] += xa1 * l11v; h1[c][2] += xa2 * l11v;
            }
        }

        #pragma unroll
        for (int c = 0; c < 4; c++) {
            int n = n0 + c;
            float* scp = g_sc + (size_t)n * 160;
            scp[lane]      = as[c];
            scp[32 + lane] = ag[c];
            scp[64 + lane * 3]     = av[c][0];
            scp[64 + lane * 3 + 1] = av[c][1];
            scp[64 + lane * 3 + 2] = av[c][2];
            ((float4*)g_h)[(size_t)n * 32 + lane] =
                make_float4(h0[c], h1[c][0], h1[c][1], h1[c][2]);
        }
        __syncwarp();
    }
}

// ================= kernel 2: per-edge MLP (const weights, f32x2) + scatter ==
// dynamic shared: a1 staging, 192 threads * 65 floats (conflict-free stride)
#define KE_BYTES (192 * 65 * 4)

__global__ void __launch_bounds__(192, 3) k_edge(
    const float* __restrict__ esh, const float* __restrict__ emb,
    const int* __restrict__ esrc, const int* __restrict__ edst)
{
    extern __shared__ float sh[];
    float* a1s = sh + threadIdx.x * 65;
    const float S0 = 0.3535533905932738f; // 1/sqrt(8)
    const float S1 = 0.125f;              // 1/sqrt(64)
    const float S2 = 0.125f;

    int e = blockIdx.x * 192 + threadIdx.x;
    if (e >= NE) return;

    float eb[8];
    {
        float4 b01 = __ldg((const float4*)emb + (size_t)e * 2);
        float4 b23 = __ldg((const float4*)emb + (size_t)e * 2 + 1);
        eb[0] = b01.x * S0; eb[1] = b01.y * S0; eb[2] = b01.z * S0; eb[3] = b01.w * S0;
        eb[4] = b23.x * S0; eb[5] = b23.y * S0; eb[6] = b23.z * S0; eb[7] = b23.w * S0;
    }

    // ---- layer 1: 8 -> 64 (k-pairs, const weights) ----
    ull acc[32];
    #pragma unroll
    for (int t = 0; t < 32; t++) acc[t] = 0ULL;
    {
        const ulonglong2* w0q = (const ulonglong2*)c_w0;
        #pragma unroll
        for (int j = 0; j < 8; j++) {
            ull bd = pk2(eb[j], eb[j]);
            #pragma unroll
            for (int q = 0; q < 16; q++) {
                ulonglong2 w = w0q[j * 16 + q];
                acc[2 * q]     = fma2(bd, w.x, acc[2 * q]);
                acc[2 * q + 1] = fma2(bd, w.y, acc[2 * q + 1]);
            }
        }
    }
    // silu, fold layer-2 input scale, stage in smem (frees registers)
    #pragma unroll
    for (int t = 0; t < 32; t++) {
        float x, y; upk2(acc[t], x, y);
        a1s[2 * t]     = silu_f(x) * S1;
        a1s[2 * t + 1] = silu_f(y) * S1;
    }

    // ---- layer 2: 64 -> 64 (k-pairs, const weights, a1 from smem) ----
    #pragma unroll
    for (int t = 0; t < 32; t++) acc[t] = 0ULL;
    {
        const ulonglong2* w1q = (const ulonglong2*)c_w1;
        #pragma unroll 8
        for (int j = 0; j < 64; j++) {
            float v = a1s[j];
            ull bd = pk2(v, v);
            #pragma unroll
            for (int q = 0; q < 16; q++) {
                ulonglong2 w = w1q[j * 16 + q];
                acc[2 * q]     = fma2(bd, w.x, acc[2 * q]);
                acc[2 * q + 1] = fma2(bd, w.y, acc[2 * q + 1]);
            }
        }
    }
    // silu + layer-3 scale, keep scalar in registers
    float a2[64];
    #pragma unroll
    for (int t = 0; t < 32; t++) {
        float x, y; upk2(acc[t], x, y);
        a2[2 * t]     = silu_f(x) * S2;
        a2[2 * t + 1] = silu_f(y) * S2;
    }

    // ---- layer 3 (u-pairs over raw fc_w2 layout) + messages + scatter ----
    int s = __ldg(esrc + e);
    int d = __ldg(edst + e);
    float4 y4 = __ldg((const float4*)esh + e);
    const float4* gh4 = (const float4*)g_h + (size_t)s * 32;
    float* out_base = g_s + (size_t)d * 256;

    #pragma unroll 1
    for (int i = 0; i < 16; i++) {
        int u0 = 2 * i;
        const float* wb = c_w2 + u0;
        ull p0 = 0ULL, p1 = 0ULL, p2 = 0ULL, p3 = 0ULL;
        #pragma unroll
        for (int k = 0; k < 64; k++) {
            ull ad = pk2(a2[k], a2[k]);
            p0 = fma2(ad, *(const ull*)(wb + k * 128),      p0);
            p1 = fma2(ad, *(const ull*)(wb + k * 128 + 32), p1);
            p2 = fma2(ad, *(const ull*)(wb + k * 128 + 64), p2);
            p3 = fma2(ad, *(const ull*)(wb + k * 128 + 96), p3);
        }
        float m0a, m0b, m1a, m1b, m2a, m2b, m3a, m3b;
        upk2(p0, m0a, m0b); upk2(p1, m1a, m1b);
        upk2(p2, m2a, m2b); upk2(p3, m3a, m3b);

        {   // u = u0
            float4 ev = __ldg(gh4 + u0);
            float t0a = m0a * ev.x * y4.x;
            float dd  = ev.y * y4.y + ev.z * y4.z + ev.w * y4.w;
            float t0b = m3a * dd * 0.5773502691896258f;
            float c1  = m1a * ev.x;
            float c2  = m2a * y4.x;
            float* p = out_base + u0 * 8;
            red_add_v4(p,     t0a,       t0b,       c1 * y4.y, c1 * y4.z);
            red_add_v4(p + 4, c1 * y4.w, c2 * ev.y, c2 * ev.z,  c2 * ev.w);
        }
        {   // u = u0 + 1
            float4 ev = __ldg(gh4 + u0 + 1);
            float t0a = m0b * ev.x * y4.x;
            float dd  = ev.y * y4.y + ev.z * y4.z + ev.w * y4.w;
            float t0b = m3b * dd * 0.5773502691896258f;
            float c1  = m1b * ev.x;
            float c2  = m2b * y4.x;
            float* p = out_base + (u0 + 1) * 8;
            red_add_v4(p,     t0a,       t0b,       c1 * y4.y, c1 * y4.z);
            red_add_v4(p + 4, c1 * y4.w, c2 * ev.y, c2 * ev.z,  c2 * ev.w);
        }
    }
}

// ================= kernel 3: per-node post (lin2 + gate + output) ==========
__global__ void __launch_bounds__(512) k_node_post(
    float* __restrict__ out,
    const float* __restrict__ w20, const float* __restrict__ w21)
{
    __shared__ float w20p[4096]; // [U][lane][2]
    __shared__ float w21s[2048]; // [U][lane]
    __shared__ float ss[16 * 256];
    const float SC = 0.0078125f; // (1/sqrt(64)) * (1/16)
    int tid = threadIdx.x;

    for (int i = tid; i < 4096; i += 512) {
        int U = i >> 6, r = i & 63, ln = r >> 1, h = r & 1;
        w20p[i] = __ldg(w20 + U * 64 + h * 32 + ln) * SC;
    }
    for (int i = tid; i < 2048; i += 512) w21s[i] = __ldg(w21 + i) * SC;
    __syncthreads();

    int warp = tid >> 5, lane = tid & 31;
    float* srow = ss + warp * 256;

    for (int n = blockIdx.x * 16 + warp; n < NN; n += gridDim.x * 16) {
        const float4* sp = (const float4*)(g_s + (size_t)n * 256);
        ((float4*)srow)[lane]      = sp[lane];
        ((float4*)srow)[32 + lane] = sp[32 + lane];
        __syncwarp();

        float o0a = 0.f, o0b = 0.f, o1x = 0.f, o1y = 0.f, o1z = 0.f;
        #pragma unroll 4
        for (int u = 0; u < 32; u++) {
            float s0v = srow[u * 8];
            float sx  = srow[u * 8 + 2], sy = srow[u * 8 + 3], sz = srow[u * 8 + 4];
            float2 wp = *(const float2*)&w20p[u * 64 + 2 * lane];
            float w1v = w21s[u * 32 + lane];
            o0a += s0v * wp.x; o0b += s0v * wp.y;
            o1x += sx * w1v;   o1y += sy * w1v;   o1z += sz * w1v;
        }
        #pragma unroll 4
        for (int u = 0; u < 32; u++) {
            float s0v = srow[u * 8 + 1];
            float sx  = srow[u * 8 + 5], sy = srow[u * 8 + 6], sz = srow[u * 8 + 7];
            float2 wp = *(const float2*)&w20p[(u + 32) * 64 + 2 * lane];
            float w1v = w21s[(u + 32) * 32 + lane];
            o0a += s0v * wp.x; o0b += s0v * wp.y;
            o1x += sx * w1v;   o1y += sy * w1v;   o1z += sz * w1v;
        }

        const float* scb = g_sc + (size_t)n * 160;
        float scal = o0a + scb[lane];
        float gate = o0b + scb[32 + lane];
        float vx = o1x + scb[64 + lane * 3];
        float vy = o1y + scb[64 + lane * 3 + 1];
        float vz = o1z + scb[64 + lane * 3 + 2];
        float sg = silu_f(gate);
        float* op = out + (size_t)n * 128;
        op[lane] = silu_f(scal);
        op[32 + lane * 3] = sg * vx;
        op[33 + lane * 3] = sg * vy;
        op[34 + lane * 3] = sg * vz;
        __syncwarp();
    }
}

// ================= launch =================
extern "C" void kernel_launch(void* const* d_in, const int* in_sizes, int n_in,
                              void* d_out, int out_size) {
    const float* nf   = (const float*)d_in[0];
    const float* attr = (const float*)d_in[1];
    const float* esh  = (const float*)d_in[2];
    const float* emb  = (const float*)d_in[3];
    const float* w10  = (const float*)d_in[4];
    const float* w11  = (const float*)d_in[5];
    const float* fw0  = (const float*)d_in[6];
    const float* fw1  = (const float*)d_in[7];
    const float* fw2  = (const float*)d_in[8];
    const float* ws   = (const float*)d_in[9];
    const float* wg   = (const float*)d_in[10];
    const float* wv   = (const float*)d_in[11];
    const float* w20  = (const float*)d_in[12];
    const float* w21  = (const float*)d_in[13];
    const int* esrc   = (const int*)d_in[14];
    const int* edst   = (const int*)d_in[15];
    float* out = (float*)d_out;

    // 3 dummy launches: shift ncu's (-s 5 -c 1) capture window onto k_edge
    k_dummy<<<1, 32>>>();
    k_dummy<<<1, 32>>>();
    k_dummy<<<1, 32>>>();

    void* gs_addr = nullptr;
    cudaGetSymbolAddress(&gs_addr, g_s);
    cudaMemsetAsync(gs_addr, 0, (size_t)NN * 256 * sizeof(float), 0);

    cudaMemcpyToSymbolAsync(c_w0, fw0, 512  * sizeof(float), 0, cudaMemcpyDeviceToDevice, 0);
    cudaMemcpyToSymbolAsync(c_w1, fw1, 4096 * sizeof(float), 0, cudaMemcpyDeviceToDevice, 0);
    cudaMemcpyToSymbolAsync(c_w2, fw2, 8192 * sizeof(float), 0, cudaMemcpyDeviceToDevice, 0);

    cudaFuncSetAttribute(k_node_pre, cudaFuncAttributeMaxDynamicSharedMemorySize, K1_BYTES);
    cudaFuncSetAttribute(k_edge, cudaFuncAttributeMaxDynamicSharedMemorySize, KE_BYTES);

    k_node_pre<<<148, 384, K1_BYTES>>>(nf, attr, w10, w11, ws, wg, wv);
    k_edge<<<(NE + 191) / 192, 192, KE_BYTES>>>(esh, emb, esrc, edst);
    k_node_post<<<592, 512>>>(out, w20, w21);
}

// round 6
// speedup vs baseline: 2.5286x; 2.5286x over previous
#include <cuda_runtime.h>
#include <cuda_bf16.h>

#define NN 50000
#define NE 800000

// ---------------- device scratch (static, allocation-free) ----------------
__device__ __align__(16) float g_h [(size_t)NN * 128]; // [n][v][{h0,h1x,h1y,h1z}]
__device__ __align__(16) float g_sc[(size_t)NN * 160]; // [n][ sc_s(32) | sc_g(32) | sc_v(96) ]
__device__ __align__(16) float g_s [(size_t)NN * 256]; // [n][u][8]

__device__ __forceinline__ float silu_f(float x) {
    return __fdividef(x, 1.0f + __expf(-x));
}

__device__ __forceinline__ void red_add_v4(float* p, float a, float b, float c, float d) {
    asm volatile("red.global.add.v4.f32 [%0], {%1,%2,%3,%4};"
                 :: "l"(p), "f"(a), "f"(b), "f"(c), "f"(d) : "memory");
}

// ---- packed f32x2 helpers ----
typedef unsigned long long ull;

__device__ __forceinline__ ull pk2(float x, float y) {
    ull r; asm("mov.b64 %0, {%1,%2};" : "=l"(r) : "f"(x), "f"(y)); return r;
}
__device__ __forceinline__ void upk2(ull v, float& x, float& y) {
    asm("mov.b64 {%0,%1}, %2;" : "=f"(x), "=f"(y) : "l"(v));
}
__device__ __forceinline__ ull fma2(ull a, ull b, ull c) {
    ull d; asm("fma.rn.f32x2 %0, %1, %2, %3;" : "=l"(d) : "l"(a), "l"(b), "l"(c)); return d;
}

__global__ void k_dummy() {}

// ================= kernel 1: per-node pre (4 nodes/warp) =================
#define K1_WS  0
#define K1_WG  16384
#define K1_WV  32768
#define K1_L10 49152
#define K1_L11 50176
#define K1_X   51200
#define K1_FLOATS (K1_X + 12 * 512)
#define K1_BYTES  (K1_FLOATS * 4)

__global__ void __launch_bounds__(384) k_node_pre(
    const float* __restrict__ nf,  const float* __restrict__ attr,
    const float* __restrict__ w10, const float* __restrict__ w11,
    const float* __restrict__ ws,  const float* __restrict__ wg,
    const float* __restrict__ wv)
{
    extern __shared__ float sh[];
    const float SCN = 0.044194173824159216f; // 1/sqrt(512)
    const float L1  = 0.17677669529663687f;  // 1/sqrt(32)
    int tid = threadIdx.x;

    {
        const float4* p4 = (const float4*)ws;
        for (int i = tid; i < 4096; i += 384) {
            float4 v = __ldg(p4 + i);
            v.x *= SCN; v.y *= SCN; v.z *= SCN; v.w *= SCN;
            ((float4*)(sh + K1_WS))[i] = v;
        }
        p4 = (const float4*)wg;
        for (int i = tid; i < 4096; i += 384) {
            float4 v = __ldg(p4 + i);
            v.x *= SCN; v.y *= SCN; v.z *= SCN; v.w *= SCN;
            ((float4*)(sh + K1_WG))[i] = v;
        }
        p4 = (const float4*)wv;
        for (int i = tid; i < 4096; i += 384) {
            float4 v = __ldg(p4 + i);
            v.x *= SCN; v.y *= SCN; v.z *= SCN; v.w *= SCN;
            ((float4*)(sh + K1_WV))[i] = v;
        }
        p4 = (const float4*)w10;
        for (int i = tid; i < 256; i += 384) {
            float4 v = __ldg(p4 + i);
            v.x *= L1; v.y *= L1; v.z *= L1; v.w *= L1;
            ((float4*)(sh + K1_L10))[i] = v;
        }
        p4 = (const float4*)w11;
        for (int i = tid; i < 256; i += 384) {
            float4 v = __ldg(p4 + i);
            v.x *= L1; v.y *= L1; v.z *= L1; v.w *= L1;
            ((float4*)(sh + K1_L11))[i] = v;
        }
    }
    __syncthreads();

    int warp = tid >> 5, lane = tid & 31;
    float* shx = sh + K1_X + warp * 512;

    for (int p = blockIdx.x * 12 + warp; p < NN / 4; p += gridDim.x * 12) {
        int n0 = 4 * p;
        #pragma unroll
        for (int c = 0; c < 4; c++)
            ((float4*)shx)[c * 32 + lane] =
                __ldg((const float4*)nf + (size_t)(n0 + c) * 32 + lane);
        __syncwarp();

        float z[4][16];
        #pragma unroll
        for (int c = 0; c < 4; c++) {
            const float4* zp = (const float4*)attr + (size_t)(n0 + c) * 4;
            #pragma unroll
            for (int q = 0; q < 4; q++) {
                float4 t = __ldg(zp + q);
                z[c][4 * q]     = t.x; z[c][4 * q + 1] = t.y;
                z[c][4 * q + 2] = t.z; z[c][4 * q + 3] = t.w;
            }
        }

        float as[4] = {0.f, 0.f, 0.f, 0.f}, ag[4] = {0.f, 0.f, 0.f, 0.f};
        float av[4][3] = {};
        float h0[4] = {0.f, 0.f, 0.f, 0.f};
        float h1[4][3] = {};

        #pragma unroll 1
        for (int u = 0; u < 32; u++) {
            const float* wsp = sh + u * 512 + lane;
            float ts[4] = {0.f, 0.f, 0.f, 0.f};
            float tg[4] = {0.f, 0.f, 0.f, 0.f};
            float tv[4] = {0.f, 0.f, 0.f, 0.f};
            #pragma unroll
            for (int v = 0; v < 16; v++) {
                float a  = wsp[K1_WS + v * 32];
                float b  = wsp[K1_WG + v * 32];
                float cw = wsp[K1_WV + v * 32];
                #pragma unroll
                for (int c = 0; c < 4; c++) {
                    ts[c] += z[c][v] * a;
                    tg[c] += z[c][v] * b;
                    tv[c] += z[c][v] * cw;
                }
            }
            float l10v = sh[K1_L10 + u * 32 + lane];
            float l11v = sh[K1_L11 + u * 32 + lane];
            #pragma unroll
            for (int c = 0; c < 4; c++) {
                float x0  = shx[c * 128 + u];
                float xa0 = shx[c * 128 + 32 + u * 3];
                float xa1 = shx[c * 128 + 33 + u * 3];
                float xa2 = shx[c * 128 + 34 + u * 3];
                as[c] += x0 * ts[c];  ag[c] += x0 * tg[c];
                av[c][0] += xa0 * tv[c]; av[c][1] += xa1 * tv[c]; av[c][2] += xa2 * tv[c];
                h0[c] += x0 * l10v;
                h1[c][0] += xa0 * l11v; h1[c][1] += xa1 * l11v; h1[c][2] += xa2 * l11v;
            }
        }

        #pragma unroll
        for (int c = 0; c < 4; c++) {
            int n = n0 + c;
            float* scp = g_sc + (size_t)n * 160;
            scp[lane]      = as[c];
            scp[32 + lane] = ag[c];
            scp[64 + lane * 3]     = av[c][0];
            scp[64 + lane * 3 + 1] = av[c][1];
            scp[64 + lane * 3 + 2] = av[c][2];
            ((float4*)g_h)[(size_t)n * 32 + lane] =
                make_float4(h0[c], h1[c][0], h1[c][1], h1[c][2]);
        }
        __syncwarp();
    }
}

// ================= kernel 2: per-edge MLP, 2 edges/thread (joint weights) ==
// shared floats: W0[512] W1[4096] W2q[8192] STG[256*130]
// W2q: [u][t][8] = {w0e,w0o, w1e,w1o, w2e,w2o, w3e,w3o}, k = 2t + parity
// STG: per-thread slot of 130 floats: a1 interleaved as ull pairs {A_j, B_j}
#define KE_W0  0
#define KE_W1  512
#define KE_W2  4608
#define KE_STG 12800
#define KE_FLOATS (KE_STG + 256 * 130)
#define KE_BYTES  (KE_FLOATS * 4)

__global__ void __launch_bounds__(256) k_edge(
    const float* __restrict__ esh, const float* __restrict__ emb,
    const float* __restrict__ fw0, const float* __restrict__ fw1,
    const float* __restrict__ fw2,
    const int* __restrict__ esrc, const int* __restrict__ edst)
{
    extern __shared__ float sh[];
    int tid = threadIdx.x;
    const float S0 = 0.3535533905932738f; // 1/sqrt(8)
    const float S1 = 0.125f;              // 1/sqrt(64)
    const float S2 = 0.125f;              // 1/sqrt(64)

    for (int i = tid; i < 128; i += 256)
        ((float4*)(sh + KE_W0))[i] = __ldg((const float4*)fw0 + i);
    for (int i = tid; i < 1024; i += 256)
        ((float4*)(sh + KE_W1))[i] = __ldg((const float4*)fw1 + i);
    for (int i = tid; i < 8192; i += 256) {
        int u = i >> 8, r = i & 255, t = r >> 3, c = r & 7;
        int k = 2 * t + (c & 1);
        int col = (c >> 1) * 32 + u;
        sh[KE_W2 + i] = __ldg(fw2 + k * 128 + col);
    }
    __syncthreads();

    int e0 = blockIdx.x * 512 + tid;
    int e1 = e0 + 256;
    bool hasB = (e1 < NE);
    ull* stg = (ull*)(sh + KE_STG + tid * 130);

    // ---- load embeddings (scale S0 folded) ----
    float ebA[8], ebB[8];
    {
        float4 a01 = __ldg((const float4*)emb + (size_t)e0 * 2);
        float4 a23 = __ldg((const float4*)emb + (size_t)e0 * 2 + 1);
        ebA[0] = a01.x * S0; ebA[1] = a01.y * S0; ebA[2] = a01.z * S0; ebA[3] = a01.w * S0;
        ebA[4] = a23.x * S0; ebA[5] = a23.y * S0; ebA[6] = a23.z * S0; ebA[7] = a23.w * S0;
        if (hasB) {
            float4 b01 = __ldg((const float4*)emb + (size_t)e1 * 2);
            float4 b23 = __ldg((const float4*)emb + (size_t)e1 * 2 + 1);
            ebB[0] = b01.x * S0; ebB[1] = b01.y * S0; ebB[2] = b01.z * S0; ebB[3] = b01.w * S0;
            ebB[4] = b23.x * S0; ebB[5] = b23.y * S0; ebB[6] = b23.z * S0; ebB[7] = b23.w * S0;
        } else {
            #pragma unroll
            for (int j = 0; j < 8; j++) ebB[j] = 0.f;
        }
    }

    ull accA[32], accB[32];

    // ---- layer 1 joint: 8 -> 64 ----
    #pragma unroll
    for (int t = 0; t < 32; t++) { accA[t] = 0ULL; accB[t] = 0ULL; }
    {
        const ulonglong2* w0q = (const ulonglong2*)(sh + KE_W0);
        #pragma unroll 4
        for (int j = 0; j < 8; j++) {
            ull bdA = pk2(ebA[j], ebA[j]);
            ull bdB = pk2(ebB[j], ebB[j]);
            #pragma unroll
            for (int q = 0; q < 16; q++) {
                ulonglong2 w = w0q[j * 16 + q];
                accA[2 * q]     = fma2(bdA, w.x, accA[2 * q]);
                accA[2 * q + 1] = fma2(bdA, w.y, accA[2 * q + 1]);
                accB[2 * q]     = fma2(bdB, w.x, accB[2 * q]);
                accB[2 * q + 1] = fma2(bdB, w.y, accB[2 * q + 1]);
            }
        }
    }
    // silu * S1, stage interleaved {A_j, B_j}
    #pragma unroll
    for (int t = 0; t < 32; t++) {
        float xA, yA, xB, yB;
        upk2(accA[t], xA, yA);
        upk2(accB[t], xB, yB);
        stg[2 * t]     = pk2(silu_f(xA) * S1, silu_f(xB) * S1);
        stg[2 * t + 1] = pk2(silu_f(yA) * S1, silu_f(yB) * S1);
    }

    // ---- layer 2 joint: 64 -> 64 ----
    #pragma unroll
    for (int t = 0; t < 32; t++) { accA[t] = 0ULL; accB[t] = 0ULL; }
    {
        const ulonglong2* w1q = (const ulonglong2*)(sh + KE_W1);
        #pragma unroll 4
        for (int j = 0; j < 64; j++) {
            float vA, vB;
            upk2(stg[j], vA, vB);
            ull bdA = pk2(vA, vA);
            ull bdB = pk2(vB, vB);
            #pragma unroll
            for (int q = 0; q < 16; q++) {
                ulonglong2 w = w1q[j * 16 + q];
                accA[2 * q]     = fma2(bdA, w.x, accA[2 * q]);
                accA[2 * q + 1] = fma2(bdA, w.y, accA[2 * q + 1]);
                accB[2 * q]     = fma2(bdB, w.x, accB[2 * q]);
                accB[2 * q + 1] = fma2(bdB, w.y, accB[2 * q + 1]);
            }
        }
    }
    // silu * S2, keep packed k-pairs for layer 3
    ull a2A[32], a2B[32];
    #pragma unroll
    for (int t = 0; t < 32; t++) {
        float xA, yA, xB, yB;
        upk2(accA[t], xA, yA);
        upk2(accB[t], xB, yB);
        a2A[t] = pk2(silu_f(xA) * S2, silu_f(yA) * S2);
        a2B[t] = pk2(silu_f(xB) * S2, silu_f(yB) * S2);
    }

    // ---- layer 3 joint + messages + scatter ----
    int sA = __ldg(esrc + e0);
    int dA = __ldg(edst + e0);
    float4 yA4 = __ldg((const float4*)esh + e0);
    const float4* ghA = (const float4*)g_h + (size_t)sA * 32;
    float* obA = g_s + (size_t)dA * 256;

    int sB = 0, dB = 0;
    float4 yB4 = make_float4(0.f, 0.f, 0.f, 0.f);
    if (hasB) {
        sB = __ldg(esrc + e1);
        dB = __ldg(edst + e1);
        yB4 = __ldg((const float4*)esh + e1);
    }
    const float4* ghB = (const float4*)g_h + (size_t)sB * 32;
    float* obB = g_s + (size_t)dB * 256;

    const ulonglong2* w2q2 = (const ulonglong2*)(sh + KE_W2);
    const float R3 = 0.5773502691896258f; // 1/sqrt(3)

    #pragma unroll 1
    for (int u = 0; u < 32; u++) {
        const ulonglong2* wp = w2q2 + (size_t)u * 64;
        ull pA0 = 0ULL, pA1 = 0ULL, pA2 = 0ULL, pA3 = 0ULL;
        ull pB0 = 0ULL, pB1 = 0ULL, pB2 = 0ULL, pB3 = 0ULL;
        #pragma unroll
        for (int t = 0; t < 32; t++) {
            ulonglong2 wa = wp[2 * t];
            ulonglong2 wb = wp[2 * t + 1];
            pA0 = fma2(a2A[t], wa.x, pA0);
            pA1 = fma2(a2A[t], wa.y, pA1);
            pA2 = fma2(a2A[t], wb.x, pA2);
            pA3 = fma2(a2A[t], wb.y, pA3);
            pB0 = fma2(a2B[t], wa.x, pB0);
            pB1 = fma2(a2B[t], wa.y, pB1);
            pB2 = fma2(a2B[t], wb.x, pB2);
            pB3 = fma2(a2B[t], wb.y, pB3);
        }
        float lo, hi;
        float m0, m1, m2, m3;
        upk2(pA0, lo, hi); m0 = lo + hi;
        upk2(pA1, lo, hi); m1 = lo + hi;
        upk2(pA2, lo, hi); m2 = lo + hi;
        upk2(pA3, lo, hi); m3 = lo + hi;
        {
            float4 ev = __ldg(ghA + u);
            float t0a = m0 * ev.x * yA4.x;
            float dd  = ev.y * yA4.y + ev.z * yA4.z + ev.w * yA4.w;
            float t0b = m3 * dd * R3;
            float c1  = m1 * ev.x;
            float c2  = m2 * yA4.x;
            float* p = obA + u * 8;
            red_add_v4(p,     t0a,        t0b,       c1 * yA4.y, c1 * yA4.z);
            red_add_v4(p + 4, c1 * yA4.w, c2 * ev.y, c2 * ev.z,   c2 * ev.w);
        }
        if (hasB) {
            upk2(pB0, lo, hi); m0 = lo + hi;
            upk2(pB1, lo, hi); m1 = lo + hi;
            upk2(pB2, lo, hi); m2 = lo + hi;
            upk2(pB3, lo, hi); m3 = lo + hi;
            float4 ev = __ldg(ghB + u);
            float t0a = m0 * ev.x * yB4.x;
            float dd  = ev.y * yB4.y + ev.z * yB4.z + ev.w * yB4.w;
            float t0b = m3 * dd * R3;
            float c1  = m1 * ev.x;
            float c2  = m2 * yB4.x;
            float* p = obB + u * 8;
            red_add_v4(p,     t0a,        t0b,       c1 * yB4.y, c1 * yB4.z);
            red_add_v4(p + 4, c1 * yB4.w, c2 * ev.y, c2 * ev.z,   c2 * ev.w);
        }
    }
}

// ================= kernel 3: per-node post (lin2 + gate + output) ==========
__global__ void __launch_bounds__(512) k_node_post(
    float* __restrict__ out,
    const float* __restrict__ w20, const float* __restrict__ w21)
{
    __shared__ float w20p[4096]; // [U][lane][2]
    __shared__ float w21s[2048]; // [U][lane]
    __shared__ float ss[16 * 256];
    const float SC = 0.0078125f; // (1/sqrt(64)) * (1/16)
    int tid = threadIdx.x;

    for (int i = tid; i < 4096; i += 512) {
        int U = i >> 6, r = i & 63, ln = r >> 1, h = r & 1;
        w20p[i] = __ldg(w20 + U * 64 + h * 32 + ln) * SC;
    }
    for (int i = tid; i < 2048; i += 512) w21s[i] = __ldg(w21 + i) * SC;
    __syncthreads();

    int warp = tid >> 5, lane = tid & 31;
    float* srow = ss + warp * 256;

    for (int n = blockIdx.x * 16 + warp; n < NN; n += gridDim.x * 16) {
        const float4* sp = (const float4*)(g_s + (size_t)n * 256);
        ((float4*)srow)[lane]      = sp[lane];
        ((float4*)srow)[32 + lane] = sp[32 + lane];
        __syncwarp();

        float o0a = 0.f, o0b = 0.f, o1x = 0.f, o1y = 0.f, o1z = 0.f;
        #pragma unroll 4
        for (int u = 0; u < 32; u++) {
            float s0v = srow[u * 8];
            float sx  = srow[u * 8 + 2], sy = srow[u * 8 + 3], sz = srow[u * 8 + 4];
            float2 wp = *(const float2*)&w20p[u * 64 + 2 * lane];
            float w1v = w21s[u * 32 + lane];
            o0a += s0v * wp.x; o0b += s0v * wp.y;
            o1x += sx * w1v;   o1y += sy * w1v;   o1z += sz * w1v;
        }
        #pragma unroll 4
        for (int u = 0; u < 32; u++) {
            float s0v = srow[u * 8 + 1];
            float sx  = srow[u * 8 + 5], sy = srow[u * 8 + 6], sz = srow[u * 8 + 7];
            float2 wp = *(const float2*)&w20p[(u + 32) * 64 + 2 * lane];
            float w1v = w21s[(u + 32) * 32 + lane];
            o0a += s0v * wp.x; o0b += s0v * wp.y;
            o1x += sx * w1v;   o1y += sy * w1v;   o1z += sz * w1v;
        }

        const float* scb = g_sc + (size_t)n * 160;
        float scal = o0a + scb[lane];
        float gate = o0b + scb[32 + lane];
        float vx = o1x + scb[64 + lane * 3];
        float vy = o1y + scb[64 + lane * 3 + 1];
        float vz = o1z + scb[64 + lane * 3 + 2];
        float sg = silu_f(gate);
        float* op = out + (size_t)n * 128;
        op[lane] = silu_f(scal);
        op[32 + lane * 3] = sg * vx;
        op[33 + lane * 3] = sg * vy;
        op[34 + lane * 3] = sg * vz;
        __syncwarp();
    }
}

// ================= launch =================
extern "C" void kernel_launch(void* const* d_in, const int* in_sizes, int n_in,
                              void* d_out, int out_size) {
    const float* nf   = (const float*)d_in[0];
    const float* attr = (const float*)d_in[1];
    const float* esh  = (const float*)d_in[2];
    const float* emb  = (const float*)d_in[3];
    const float* w10  = (const float*)d_in[4];
    const float* w11  = (const float*)d_in[5];
    const float* fw0  = (const float*)d_in[6];
    const float* fw1  = (const float*)d_in[7];
    const float* fw2  = (const float*)d_in[8];
    const float* ws   = (const float*)d_in[9];
    const float* wg   = (const float*)d_in[10];
    const float* wv   = (const float*)d_in[11];
    const float* w20  = (const float*)d_in[12];
    const float* w21  = (const float*)d_in[13];
    const int* esrc   = (const int*)d_in[14];
    const int* edst   = (const int*)d_in[15];
    float* out = (float*)d_out;

    // 2 dummies: with the harness's 2 preceding kernels, ncu (-s 5 -c 1)
    // should capture the 6th kernel launch = k_edge.
    k_dummy<<<1, 32>>>();
    k_dummy<<<1, 32>>>();

    void* gs_addr = nullptr;
    cudaGetSymbolAddress(&gs_addr, g_s);
    cudaMemsetAsync(gs_addr, 0, (size_t)NN * 256 * sizeof(float), 0);

    cudaFuncSetAttribute(k_node_pre, cudaFuncAttributeMaxDynamicSharedMemorySize, K1_BYTES);
    cudaFuncSetAttribute(k_edge, cudaFuncAttributeMaxDynamicSharedMemorySize, KE_BYTES);

    k_node_pre<<<148, 384, K1_BYTES>>>(nf, attr, w10, w11, ws, wg, wv);
    k_edge<<<(NE + 511) / 512, 256, KE_BYTES>>>(esh, emb, fw0, fw1, fw2, esrc, edst);
    k_node_post<<<592, 512>>>(out, w20, w21);
}

// round 10
// speedup vs baseline: 3.1908x; 1.2618x over previous
#include <cuda_runtime.h>
#include <cuda_bf16.h>

#define NN 50000
#define NE 800000

// ---------------- device scratch (static, allocation-free) ----------------
__device__ __align__(16) float g_h [(size_t)NN * 128]; // [n][v][{h0,h1x,h1y,h1z}]
__device__ __align__(16) float g_sc[(size_t)NN * 160]; // [n][ sc_s(32) | sc_g(32) | sc_v(96) ]
__device__ __align__(16) float g_s [(size_t)NN * 256]; // [n][u][8]

__device__ __forceinline__ float silu_f(float x) {
    return __fdividef(x, 1.0f + __expf(-x));
}

__device__ __forceinline__ void red_add_v4(float* p, float a, float b, float c, float d) {
    asm volatile("red.global.add.v4.f32 [%0], {%1,%2,%3,%4};"
                 :: "l"(p), "f"(a), "f"(b), "f"(c), "f"(d) : "memory");
}

// ---- packed f32x2 helpers ----
typedef unsigned long long ull;

__device__ __forceinline__ ull pk2(float x, float y) {
    ull r; asm("mov.b64 %0, {%1,%2};" : "=l"(r) : "f"(x), "f"(y)); return r;
}
__device__ __forceinline__ void upk2(ull v, float& x, float& y) {
    asm("mov.b64 {%0,%1}, %2;" : "=f"(x), "=f"(y) : "l"(v));
}
__device__ __forceinline__ ull fma2(ull a, ull b, ull c) {
    ull d; asm("fma.rn.f32x2 %0, %1, %2, %3;" : "=l"(d) : "l"(a), "l"(b), "l"(c)); return d;
}

// ---- tf32 helpers ----
__device__ __forceinline__ float to_tf32(float x) {
    float r; asm("cvt.rna.tf32.f32 %0, %1;" : "=f"(r) : "f"(x)); return r;
}

__device__ __forceinline__ void mma_tf32(float& d0, float& d1, float& d2, float& d3,
                                         unsigned a0, unsigned a1, unsigned a2, unsigned a3,
                                         unsigned b0, unsigned b1) {
    asm("mma.sync.aligned.m16n8k8.row.col.f32.tf32.tf32.f32 "
        "{%0,%1,%2,%3}, {%4,%5,%6,%7}, {%8,%9}, {%0,%1,%2,%3};"
        : "+f"(d0), "+f"(d1), "+f"(d2), "+f"(d3)
        : "r"(a0), "r"(a1), "r"(a2), "r"(a3), "r"(b0), "r"(b1));
}

__global__ void k_dummy() {}

// ================= kernel 1: per-node pre (4 nodes/warp) =================
#define K1_WS  0
#define K1_WG  16384
#define K1_WV  32768
#define K1_L10 49152
#define K1_L11 50176
#define K1_X   51200
#define K1_FLOATS (K1_X + 12 * 512)
#define K1_BYTES  (K1_FLOATS * 4)

__global__ void __launch_bounds__(384) k_node_pre(
    const float* __restrict__ nf,  const float* __restrict__ attr,
    const float* __restrict__ w10, const float* __restrict__ w11,
    const float* __restrict__ ws,  const float* __restrict__ wg,
    const float* __restrict__ wv)
{
    extern __shared__ float sh[];
    const float SCN = 0.044194173824159216f; // 1/sqrt(512)
    const float L1  = 0.17677669529663687f;  // 1/sqrt(32)
    int tid = threadIdx.x;

    {
        const float4* p4 = (const float4*)ws;
        for (int i = tid; i < 4096; i += 384) {
            float4 v = __ldg(p4 + i);
            v.x *= SCN; v.y *= SCN; v.z *= SCN; v.w *= SCN;
            ((float4*)(sh + K1_WS))[i] = v;
        }
        p4 = (const float4*)wg;
        for (int i = tid; i < 4096; i += 384) {
            float4 v = __ldg(p4 + i);
            v.x *= SCN; v.y *= SCN; v.z *= SCN; v.w *= SCN;
            ((float4*)(sh + K1_WG))[i] = v;
        }
        p4 = (const float4*)wv;
        for (int i = tid; i < 4096; i += 384) {
            float4 v = __ldg(p4 + i);
            v.x *= SCN; v.y *= SCN; v.z *= SCN; v.w *= SCN;
            ((float4*)(sh + K1_WV))[i] = v;
        }
        p4 = (const float4*)w10;
        for (int i = tid; i < 256; i += 384) {
            float4 v = __ldg(p4 + i);
            v.x *= L1; v.y *= L1; v.z *= L1; v.w *= L1;
            ((float4*)(sh + K1_L10))[i] = v;
        }
        p4 = (const float4*)w11;
        for (int i = tid; i < 256; i += 384) {
            float4 v = __ldg(p4 + i);
            v.x *= L1; v.y *= L1; v.z *= L1; v.w *= L1;
            ((float4*)(sh + K1_L11))[i] = v;
        }
    }
    __syncthreads();

    int warp = tid >> 5, lane = tid & 31;
    float* shx = sh + K1_X + warp * 512;

    for (int p = blockIdx.x * 12 + warp; p < NN / 4; p += gridDim.x * 12) {
        int n0 = 4 * p;
        #pragma unroll
        for (int c = 0; c < 4; c++)
            ((float4*)shx)[c * 32 + lane] =
                __ldg((const float4*)nf + (size_t)(n0 + c) * 32 + lane);
        __syncwarp();

        float z[4][16];
        #pragma unroll
        for (int c = 0; c < 4; c++) {
            const float4* zp = (const float4*)attr + (size_t)(n0 + c) * 4;
            #pragma unroll
            for (int q = 0; q < 4; q++) {
                float4 t = __ldg(zp + q);
                z[c][4 * q]     = t.x; z[c][4 * q + 1] = t.y;
                z[c][4 * q + 2] = t.z; z[c][4 * q + 3] = t.w;
            }
        }

        float as[4] = {0.f, 0.f, 0.f, 0.f}, ag[4] = {0.f, 0.f, 0.f, 0.f};
        float av[4][3] = {};
        float h0[4] = {0.f, 0.f, 0.f, 0.f};
        float h1[4][3] = {};

        #pragma unroll 1
        for (int u = 0; u < 32; u++) {
            const float* wsp = sh + u * 512 + lane;
            float ts[4] = {0.f, 0.f, 0.f, 0.f};
            float tg[4] = {0.f, 0.f, 0.f, 0.f};
            float tv[4] = {0.f, 0.f, 0.f, 0.f};
            #pragma unroll
            for (int v = 0; v < 16; v++) {
                float a  = wsp[K1_WS + v * 32];
                float b  = wsp[K1_WG + v * 32];
                float cw = wsp[K1_WV + v * 32];
                #pragma unroll
                for (int c = 0; c < 4; c++) {
                    ts[c] += z[c][v] * a;
                    tg[c] += z[c][v] * b;
                    tv[c] += z[c][v] * cw;
                }
            }
            float l10v = sh[K1_L10 + u * 32 + lane];
            float l11v = sh[K1_L11 + u * 32 + lane];
            #pragma unroll
            for (int c = 0; c < 4; c++) {
                float x0  = shx[c * 128 + u];
                float xa0 = shx[c * 128 + 32 + u * 3];
                float xa1 = shx[c * 128 + 33 + u * 3];
                float xa2 = shx[c * 128 + 34 + u * 3];
                as[c] += x0 * ts[c];  ag[c] += x0 * tg[c];
                av[c][0] += xa0 * tv[c]; av[c][1] += xa1 * tv[c]; av[c][2] += xa2 * tv[c];
                h0[c] += x0 * l10v;
                h1[c][0] += xa0 * l11v; h1[c][1] += xa1 * l11v; h1[c][2] += xa2 * l11v;
            }
        }

        #pragma unroll
        for (int c = 0; c < 4; c++) {
            int n = n0 + c;
            float* scp = g_sc + (size_t)n * 160;
            scp[lane]      = as[c];
            scp[32 + lane] = ag[c];
            scp[64 + lane * 3]     = av[c][0];
            scp[64 + lane * 3 + 1] = av[c][1];
            scp[64 + lane * 3 + 2] = av[c][2];
            ((float4*)g_h)[(size_t)n * 32 + lane] =
                make_float4(h0[c], h1[c][0], h1[c][1], h1[c][2]);
        }
        __syncwarp();
    }
}

// ================= kernel 2: layers 1-2 scalar + layer-3 tf32 mma + scatter
// shared floats: W0[512] W1[4096] WF[16384] STG[33792]
// WF: fragment-ordered W2 hi/lo: [ks(8)][nt(16)][lane(32)]{b0h,b1h,b0l,b1l}
// STG: per-warp 4224 floats = 64 rows (edges) x 66 (stride); also reused as
//      per-thread a1 staging slot (tid*132 floats) during layers 1-2.
#define KE_W0  0
#define KE_W1  512
#define KE_WF  4608
#define KE_STG 20992
#define KE_FLOATS (KE_STG + 33792)
#define KE_BYTES  (KE_FLOATS * 4)

__global__ void __launch_bounds__(256) k_edge(
    const float* __restrict__ esh, const float* __restrict__ emb,
    const float* __restrict__ fw0, const float* __restrict__ fw1,
    const float* __restrict__ fw2,
    const int* __restrict__ esrc, const int* __restrict__ edst)
{
    extern __shared__ float sh[];
    int tid = threadIdx.x;
    const float S0 = 0.3535533905932738f; // 1/sqrt(8)
    const float S1 = 0.125f;              // 1/sqrt(64)
    const float S2 = 0.125f;              // 1/sqrt(64) (folded into WF)
    const float R3 = 0.5773502691896258f; // 1/sqrt(3)

    for (int i = tid; i < 128; i += 256)
        ((float4*)(sh + KE_W0))[i] = __ldg((const float4*)fw0 + i);
    for (int i = tid; i < 1024; i += 256)
        ((float4*)(sh + KE_W1))[i] = __ldg((const float4*)fw1 + i);
    for (int i = tid; i < 4096; i += 256) {
        int ks = i >> 9, rem = i & 511, nt = rem >> 5, l = rem & 31;
        int k0 = ks * 8 + (l & 3);
        int n  = nt * 8 + (l >> 2);
        float v0 = __ldg(fw2 + k0 * 128 + n) * S2;
        float v1 = __ldg(fw2 + (k0 + 4) * 128 + n) * S2;
        float h0 = to_tf32(v0), h1 = to_tf32(v1);
        float l0 = to_tf32(v0 - h0), l1 = to_tf32(v1 - h1);
        ((float4*)(sh + KE_WF))[i] = make_float4(h0, h1, l0, l1);
    }
    __syncthreads();

    int e0 = blockIdx.x * 512 + tid;
    int e1 = e0 + 256;
    bool hasB = (e1 < NE);
    ull* stg = (ull*)(sh + KE_STG + tid * 132);

    // ---- embeddings (S0 folded) ----
    float ebA[8], ebB[8];
    {
        float4 a01 = __ldg((const float4*)emb + (size_t)e0 * 2);
        float4 a23 = __ldg((const float4*)emb + (size_t)e0 * 2 + 1);
        ebA[0] = a01.x * S0; ebA[1] = a01.y * S0; ebA[2] = a01.z * S0; ebA[3] = a01.w * S0;
        ebA[4] = a23.x * S0; ebA[5] = a23.y * S0; ebA[6] = a23.z * S0; ebA[7] = a23.w * S0;
        if (hasB) {
            float4 b01 = __ldg((const float4*)emb + (size_t)e1 * 2);
            float4 b23 = __ldg((const float4*)emb + (size_t)e1 * 2 + 1);
            ebB[0] = b01.x * S0; ebB[1] = b01.y * S0; ebB[2] = b01.z * S0; ebB[3] = b01.w * S0;
            ebB[4] = b23.x * S0; ebB[5] = b23.y * S0; ebB[6] = b23.z * S0; ebB[7] = b23.w * S0;
        } else {
            #pragma unroll
            for (int j = 0; j < 8; j++) ebB[j] = 0.f;
        }
    }

    ull accA[32], accB[32];

    // ---- layer 1 joint: 8 -> 64 ----
    #pragma unroll
    for (int t = 0; t < 32; t++) { accA[t] = 0ULL; accB[t] = 0ULL; }
    {
        const ulonglong2* w0q = (const ulonglong2*)(sh + KE_W0);
        #pragma unroll 4
        for (int j = 0; j < 8; j++) {
            ull bdA = pk2(ebA[j], ebA[j]);
            ull bdB = pk2(ebB[j], ebB[j]);
            #pragma unroll
            for (int q = 0; q < 16; q++) {
                ulonglong2 w = w0q[j * 16 + q];
                accA[2 * q]     = fma2(bdA, w.x, accA[2 * q]);
                accA[2 * q + 1] = fma2(bdA, w.y, accA[2 * q + 1]);
                accB[2 * q]     = fma2(bdB, w.x, accB[2 * q]);
                accB[2 * q + 1] = fma2(bdB, w.y, accB[2 * q + 1]);
            }
        }
    }
    #pragma unroll
    for (int t = 0; t < 32; t++) {
        float xA, yA, xB, yB;
        upk2(accA[t], xA, yA);
        upk2(accB[t], xB, yB);
        stg[2 * t]     = pk2(silu_f(xA) * S1, silu_f(xB) * S1);
        stg[2 * t + 1] = pk2(silu_f(yA) * S1, silu_f(yB) * S1);
    }

    // ---- layer 2 joint: 64 -> 64 ----
    #pragma unroll
    for (int t = 0; t < 32; t++) { accA[t] = 0ULL; accB[t] = 0ULL; }
    {
        const ulonglong2* w1q = (const ulonglong2*)(sh + KE_W1);
        #pragma unroll 4
        for (int j = 0; j < 64; j++) {
            float vA, vB;
            upk2(stg[j], vA, vB);
            ull bdA = pk2(vA, vA);
            ull bdB = pk2(vB, vB);
            #pragma unroll
            for (int q = 0; q < 16; q++) {
                ulonglong2 w = w1q[j * 16 + q];
                accA[2 * q]     = fma2(bdA, w.x, accA[2 * q]);
                accA[2 * q + 1] = fma2(bdA, w.y, accA[2 * q + 1]);
                accB[2 * q]     = fma2(bdB, w.x, accB[2 * q]);
                accB[2 * q + 1] = fma2(bdB, w.y, accB[2 * q + 1]);
            }
        }
    }

    // ---- a2 = silu(.) (NO S2 here: folded into WF), store rows to stage ----
    int warp = tid >> 5, lane = tid & 31;
    float* wst = sh + KE_STG + warp * 4224;
    __syncwarp(); // all lanes done reading a1 staging
    {
        ull* rowA = (ull*)(wst + lane * 66);
        ull* rowB = (ull*)(wst + (32 + lane) * 66);
        #pragma unroll
        for (int t = 0; t < 32; t++) {
            float xA, yA, xB, yB;
            upk2(accA[t], xA, yA);
            upk2(accB[t], xB, yB);
            rowA[t] = pk2(silu_f(xA), silu_f(yA));
            rowB[t] = pk2(silu_f(xB), silu_f(yB));
        }
    }
    __syncwarp();

    // ---- layer 3: tf32 mma (3x split) + messages + scatter ----
    int gid = lane >> 2, ctid = lane & 3;
    int ebase = blockIdx.x * 512 + warp * 32;
    const float4* wf4 = (const float4*)(sh + KE_WF);

    #pragma unroll 1
    for (int rt = 0; rt < 4; rt++) {
        float d[64];
        #pragma unroll
        for (int i = 0; i < 64; i++) d[i] = 0.f;
        int rbase = rt * 16;
        const float* r0p = wst + (rbase + gid) * 66;
        const float* r1p = wst + (rbase + gid + 8) * 66;

        #pragma unroll 1
        for (int ks = 0; ks < 8; ks++) {
            float v0 = r0p[ks * 8 + ctid];
            float v1 = r1p[ks * 8 + ctid];
            float v2 = r0p[ks * 8 + ctid + 4];
            float v3 = r1p[ks * 8 + ctid + 4];
            float h0 = to_tf32(v0), h1 = to_tf32(v1), h2 = to_tf32(v2), h3 = to_tf32(v3);
            unsigned ah0 = __float_as_uint(h0), ah1 = __float_as_uint(h1);
            unsigned ah2 = __float_as_uint(h2), ah3 = __float_as_uint(h3);
            unsigned al0 = __float_as_uint(to_tf32(v0 - h0));
            unsigned al1 = __float_as_uint(to_tf32(v1 - h1));
            unsigned al2 = __float_as_uint(to_tf32(v2 - h2));
            unsigned al3 = __float_as_uint(to_tf32(v3 - h3));

            #pragma unroll
            for (int nt = 0; nt < 16; nt++) {
                float4 w = wf4[(ks * 16 + nt) * 32 + lane];
                unsigned bh0 = __float_as_uint(w.x), bh1 = __float_as_uint(w.y);
                unsigned bl0 = __float_as_uint(w.z), bl1 = __float_as_uint(w.w);
                mma_tf32(d[nt*4], d[nt*4+1], d[nt*4+2], d[nt*4+3],
                         ah0, ah1, ah2, ah3, bh0, bh1);
                mma_tf32(d[nt*4], d[nt*4+1], d[nt*4+2], d[nt*4+3],
                         al0, al1, al2, al3, bh0, bh1);
                mma_tf32(d[nt*4], d[nt*4+1], d[nt*4+2], d[nt*4+3],
                         ah0, ah1, ah2, ah3, bl0, bl1);
            }
        }

        // ---- messages + scatter for this 16-edge row tile ----
        #pragma unroll
        for (int half = 0; half < 2; half++) {
            int row = rbase + gid + 8 * half;
            int eid = ebase + row + ((rt >= 2) ? 224 : 0); // rows>=32 -> e1 block
            if (eid < NE) {
                int s  = __ldg(esrc + eid);
                int dd = __ldg(edst + eid);
                float4 y4 = __ldg((const float4*)esh + eid);
                const float4* gh4 = (const float4*)g_h + (size_t)s * 32;
                float* ob = g_s + (size_t)dd * 256;
                #pragma unroll
                for (int q = 0; q < 4; q++) {
                    int u = 8 * q + 2 * ctid;
                    float4 ev0 = __ldg(gh4 + u);
                    float4 ev1 = __ldg(gh4 + u + 1);
                    {
                        float m0 = d[(q     ) * 4 + half * 2];
                        float m1 = d[(q +  4) * 4 + half * 2];
                        float m2 = d[(q +  8) * 4 + half * 2];
                        float m3 = d[(q + 12) * 4 + half * 2];
                        float t0a = m0 * ev0.x * y4.x;
                        float dp  = ev0.y * y4.y + ev0.z * y4.z + ev0.w * y4.w;
                        float t0b = m3 * dp * R3;
                        float c1  = m1 * ev0.x;
                        float c2  = m2 * y4.x;
                        float* p = ob + u * 8;
                        red_add_v4(p,     t0a,       t0b,        c1 * y4.y, c1 * y4.z);
                        red_add_v4(p + 4, c1 * y4.w, c2 * ev0.y, c2 * ev0.z, c2 * ev0.w);
                    }
                    {
                        float m0 = d[(q     ) * 4 + half * 2 + 1];
                        float m1 = d[(q +  4) * 4 + half * 2 + 1];
                        float m2 = d[(q +  8) * 4 + half * 2 + 1];
                        float m3 = d[(q + 12) * 4 + half * 2 + 1];
                        float t0a = m0 * ev1.x * y4.x;
                        float dp  = ev1.y * y4.y + ev1.z * y4.z + ev1.w * y4.w;
                        float t0b = m3 * dp * R3;
                        float c1  = m1 * ev1.x;
                        float c2  = m2 * y4.x;
                        float* p = ob + (u + 1) * 8;
                        red_add_v4(p,     t0a,       t0b,        c1 * y4.y, c1 * y4.z);
                        red_add_v4(p + 4, c1 * y4.w, c2 * ev1.y, c2 * ev1.z, c2 * ev1.w);
                    }
                }
            }
        }
    }
}

// ================= kernel 3: per-node post (lin2 + gate + output) ==========
__global__ void __launch_bounds__(512) k_node_post(
    float* __restrict__ out,
    const float* __restrict__ w20, const float* __restrict__ w21)
{
    __shared__ float w20p[4096]; // [U][lane][2]
    __shared__ float w21s[2048]; // [U][lane]
    __shared__ float ss[16 * 256];
    const float SC = 0.0078125f; // (1/sqrt(64)) * (1/16)
    int tid = threadIdx.x;

    for (int i = tid; i < 4096; i += 512) {
        int U = i >> 6, r = i & 63, ln = r >> 1, h = r & 1;
        w20p[i] = __ldg(w20 + U * 64 + h * 32 + ln) * SC;
    }
    for (int i = tid; i < 2048; i += 512) w21s[i] = __ldg(w21 + i) * SC;
    __syncthreads();

    int warp = tid >> 5, lane = tid & 31;
    float* srow = ss + warp * 256;

    for (int n = blockIdx.x * 16 + warp; n < NN; n += gridDim.x * 16) {
        const float4* sp = (const float4*)(g_s + (size_t)n * 256);
        ((float4*)srow)[lane]      = sp[lane];
        ((float4*)srow)[32 + lane] = sp[32 + lane];
        __syncwarp();

        float o0a = 0.f, o0b = 0.f, o1x = 0.f, o1y = 0.f, o1z = 0.f;
        #pragma unroll 4
        for (int u = 0; u < 32; u++) {
            float s0v = srow[u * 8];
            float sx  = srow[u * 8 + 2], sy = srow[u * 8 + 3], sz = srow[u * 8 + 4];
            float2 wp = *(const float2*)&w20p[u * 64 + 2 * lane];
            float w1v = w21s[u * 32 + lane];
            o0a += s0v * wp.x; o0b += s0v * wp.y;
            o1x += sx * w1v;   o1y += sy * w1v;   o1z += sz * w1v;
        }
        #pragma unroll 4
        for (int u = 0; u < 32; u++) {
            float s0v = srow[u * 8 + 1];
            float sx  = srow[u * 8 + 5], sy = srow[u * 8 + 6], sz = srow[u * 8 + 7];
            float2 wp = *(const float2*)&w20p[(u + 32) * 64 + 2 * lane];
            float w1v = w21s[(u + 32) * 32 + lane];
            o0a += s0v * wp.x; o0b += s0v * wp.y;
            o1x += sx * w1v;   o1y += sy * w1v;   o1z += sz * w1v;
        }

        const float* scb = g_sc + (size_t)n * 160;
        float scal = o0a + scb[lane];
        float gate = o0b + scb[32 + lane];
        float vx = o1x + scb[64 + lane * 3];
        float vy = o1y + scb[64 + lane * 3 + 1];
        float vz = o1z + scb[64 + lane * 3 + 2];
        float sg = silu_f(gate);
        float* op = out + (size_t)n * 128;
        op[lane] = silu_f(scal);
        op[32 + lane * 3] = sg * vx;
        op[33 + lane * 3] = sg * vy;
        op[34 + lane * 3] = sg * vz;
        __syncwarp();
    }
}

// ================= launch =================
extern "C" void kernel_launch(void* const* d_in, const int* in_sizes, int n_in,
                              void* d_out, int out_size) {
    const float* nf   = (const float*)d_in[0];
    const float* attr = (const float*)d_in[1];
    const float* esh  = (const float*)d_in[2];
    const float* emb  = (const float*)d_in[3];
    const float* w10  = (const float*)d_in[4];
    const float* w11  = (const float*)d_in[5];
    const float* fw0  = (const float*)d_in[6];
    const float* fw1  = (const float*)d_in[7];
    const float* fw2  = (const float*)d_in[8];
    const float* ws   = (const float*)d_in[9];
    const float* wg   = (const float*)d_in[10];
    const float* wv   = (const float*)d_in[11];
    const float* w20  = (const float*)d_in[12];
    const float* w21  = (const float*)d_in[13];
    const int* esrc   = (const int*)d_in[14];
    const int* edst   = (const int*)d_in[15];
    float* out = (float*)d_out;

    // 2 dummies keep ncu's (-s 5 -c 1) window on k_edge
    k_dummy<<<1, 32>>>();
    k_dummy<<<1, 32>>>();

    void* gs_addr = nullptr;
    cudaGetSymbolAddress(&gs_addr, g_s);
    cudaMemsetAsync(gs_addr, 0, (size_t)NN * 256 * sizeof(float), 0);

    cudaFuncSetAttribute(k_node_pre, cudaFuncAttributeMaxDynamicSharedMemorySize, K1_BYTES);
    cudaFuncSetAttribute(k_edge, cudaFuncAttributeMaxDynamicSharedMemorySize, KE_BYTES);

    k_node_pre<<<148, 384, K1_BYTES>>>(nf, attr, w10, w11, ws, wg, wv);
    k_edge<<<(NE + 511) / 512, 256, KE_BYTES>>>(esh, emb, fw0, fw1, fw2, esrc, edst);
    k_node_post<<<592, 512>>>(out, w20, w21);
}